// round 2
// baseline (speedup 1.0000x reference)
#include <cuda_runtime.h>
#include <cuda_bf16.h>
#include <math.h>

#define Bn 1024
#define Sn 512
#define Vn 50000
#define En 300
#define Hn 800
#define Tn 50
#define NLBLK 391            // ceil(50000/128)

// ---------------- scratch (device globals; no allocation) ----------------
__device__ float g_x[Bn * En];                    // 1.2 MB
__device__ float g_h[Bn * Hn];                    // 3.3 MB
__device__ float g_mu[Bn * Tn];
__device__ float g_lv[Bn * Tn];
__device__ float g_betaT[(size_t)Vn * 64];        // 12.8 MB: logitsT then betaT in-place
__device__ __nv_bfloat162 g_rho16[(size_t)Vn * En / 2];  // 30 MB
__device__ float g_alphaT[300 * 64];              // 76.8 KB, [k][t] zero-padded t>=50
__device__ float g_part[4 * Bn * 128];            // 2 MB head split-K partials
__device__ float g_bmax[NLBLK * 64];
__device__ float g_bsum[NLBLK * 64];
__device__ float g_rmax[64];
__device__ float g_rinv[64];
__device__ float g_recon[Bn];
__device__ float g_kl[Bn];

// ---------------- rho -> bf16 ----------------
__global__ void k_tobf16(const float* __restrict__ rho)
{
    const float4* in = (const float4*)rho;
    int n4 = Vn * En / 4;  // 3,750,000
    for (int i = blockIdx.x * blockDim.x + threadIdx.x; i < n4; i += gridDim.x * blockDim.x) {
        float4 v = in[i];
        g_rho16[2 * i]     = __floats2bfloat162_rn(v.x, v.y);
        g_rho16[2 * i + 1] = __floats2bfloat162_rn(v.z, v.w);
    }
}

// ---------------- alpha -> alphaT [k][64] (t padded to 64 with zeros) ----------------
__global__ void k_alphaT(const float* __restrict__ alpha)
{
    int idx = blockIdx.x * blockDim.x + threadIdx.x;
    if (idx < 300 * 64) {
        int k = idx >> 6, t = idx & 63;
        g_alphaT[idx] = (t < Tn) ? alpha[t * En + k] : 0.f;
    }
}

// ---------------- x[b,:] = (1/cnt) * sum_valid rho16[id,:] ----------------
__global__ void k_gather(const int* __restrict__ ids)
{
    __shared__ int sid[Sn];
    __shared__ float s_inv;
    int b = blockIdx.x, tid = threadIdx.x;  // 160 threads
    for (int i = tid; i < Sn; i += 160) {
        int v = ids[b * Sn + i];
        sid[i] = (v == 1 || v == 2) ? -1 : v;
    }
    __syncthreads();
    if (tid < 32) {
        int c = 0;
        for (int i = tid; i < Sn; i += 32) c += (sid[i] >= 0);
#pragma unroll
        for (int o = 16; o; o >>= 1) c += __shfl_down_sync(0xffffffffu, c, o);
        if (tid == 0) s_inv = 1.0f / (float)c;
    }
    __syncthreads();
    if (tid < 150) {
        float2 a0 = {0,0}, a1 = {0,0}, a2 = {0,0}, a3 = {0,0};
        float2 a4 = {0,0}, a5 = {0,0}, a6 = {0,0}, a7 = {0,0};
        const __nv_bfloat162* R = g_rho16;
#pragma unroll 1
        for (int s = 0; s < Sn; s += 8) {
            int v0 = sid[s+0], v1 = sid[s+1], v2 = sid[s+2], v3 = sid[s+3];
            int v4 = sid[s+4], v5 = sid[s+5], v6 = sid[s+6], v7 = sid[s+7];
            if (v0 >= 0) { float2 f = __bfloat1622float2(R[(size_t)v0*150 + tid]); a0.x += f.x; a0.y += f.y; }
            if (v1 >= 0) { float2 f = __bfloat1622float2(R[(size_t)v1*150 + tid]); a1.x += f.x; a1.y += f.y; }
            if (v2 >= 0) { float2 f = __bfloat1622float2(R[(size_t)v2*150 + tid]); a2.x += f.x; a2.y += f.y; }
            if (v3 >= 0) { float2 f = __bfloat1622float2(R[(size_t)v3*150 + tid]); a3.x += f.x; a3.y += f.y; }
            if (v4 >= 0) { float2 f = __bfloat1622float2(R[(size_t)v4*150 + tid]); a4.x += f.x; a4.y += f.y; }
            if (v5 >= 0) { float2 f = __bfloat1622float2(R[(size_t)v5*150 + tid]); a5.x += f.x; a5.y += f.y; }
            if (v6 >= 0) { float2 f = __bfloat1622float2(R[(size_t)v6*150 + tid]); a6.x += f.x; a6.y += f.y; }
            if (v7 >= 0) { float2 f = __bfloat1622float2(R[(size_t)v7*150 + tid]); a7.x += f.x; a7.y += f.y; }
        }
        float sx = ((a0.x+a1.x)+(a2.x+a3.x)) + ((a4.x+a5.x)+(a6.x+a7.x));
        float sy = ((a0.y+a1.y)+(a2.y+a3.y)) + ((a4.y+a5.y)+(a6.y+a7.y));
        g_x[b * En + 2*tid]     = sx * s_inv;
        g_x[b * En + 2*tid + 1] = sy * s_inv;
    }
}

// ---------------- tiled fp32 GEMM (used for h = relu(x@W1+b1)) ----------------
template <int RELU>
__global__ void k_gemm(const float* __restrict__ A, const float* __restrict__ B,
                       const float* __restrict__ bias, float* __restrict__ C,
                       int M, int N, int K)
{
    __shared__ float As[20][65];
    __shared__ float Bs[20][68];
    int tid = threadIdx.x;
    int m0 = blockIdx.y * 64, n0 = blockIdx.x * 64;
    int my = (tid >> 4) * 4, nx = (tid & 15) * 4;
    float acc[4][4] = {};
    for (int k0 = 0; k0 < K; k0 += 20) {
#pragma unroll
        for (int p = 0; p < 5; p++) {
            int idx = tid + p * 256;
            {
                int i = idx / 20, j = idx % 20;
                int row = m0 + i;
                As[j][i] = (row < M) ? A[(size_t)row * K + k0 + j] : 0.f;
            }
            {
                int j = idx / 64, i = idx % 64;
                int col = n0 + i;
                Bs[j][i] = (col < N) ? B[(size_t)(k0 + j) * N + col] : 0.f;
            }
        }
        __syncthreads();
#pragma unroll
        for (int k = 0; k < 20; k++) {
            float a0 = As[k][my+0], a1 = As[k][my+1], a2 = As[k][my+2], a3 = As[k][my+3];
            float4 bv = *reinterpret_cast<const float4*>(&Bs[k][nx]);
            acc[0][0] += a0*bv.x; acc[0][1] += a0*bv.y; acc[0][2] += a0*bv.z; acc[0][3] += a0*bv.w;
            acc[1][0] += a1*bv.x; acc[1][1] += a1*bv.y; acc[1][2] += a1*bv.z; acc[1][3] += a1*bv.w;
            acc[2][0] += a2*bv.x; acc[2][1] += a2*bv.y; acc[2][2] += a2*bv.z; acc[2][3] += a2*bv.w;
            acc[3][0] += a3*bv.x; acc[3][1] += a3*bv.y; acc[3][2] += a3*bv.z; acc[3][3] += a3*bv.w;
        }
        __syncthreads();
    }
#pragma unroll
    for (int i = 0; i < 4; i++) {
        int row = m0 + my + i;
        if (row >= M) continue;
#pragma unroll
        for (int j = 0; j < 4; j++) {
            int col = n0 + nx + j;
            if (col >= N) continue;
            float v = acc[i][j] + bias[col];
            if (RELU) v = fmaxf(v, 0.f);
            C[(size_t)row * N + col] = v;
        }
    }
}

// ---------------- head split-K stage A: partial[ks][row][c] over k-chunk of 200 ------
// grid (4 ksplit, 64 rowblk), 128 threads. c: 0..49 -> Wmu, 50..99 -> Wlv.
__global__ void k_head_part(const float* __restrict__ Wmu, const float* __restrict__ Wlv)
{
    __shared__ float Ws[50][132];
    __shared__ float hT[50][20];
    int tid = threadIdx.x;
    int ks = blockIdx.x, rb = blockIdx.y;
    int ct = tid & 31, rt = tid >> 5;
    float acc[4][4] = {};
    for (int sub = 0; sub < 4; sub++) {
        int k0 = ks * 200 + sub * 50;
        __syncthreads();
        for (int idx = tid; idx < 50 * 132; idx += 128) {
            int k = idx / 132, c = idx % 132;
            float v = 0.f;
            if (c < 50)       v = Wmu[(size_t)(k0 + k) * Tn + c];
            else if (c < 100) v = Wlv[(size_t)(k0 + k) * Tn + (c - 50)];
            Ws[k][c] = v;
        }
        for (int idx = tid; idx < 50 * 16; idx += 128) {
            int r = idx / 50, k = idx % 50;
            hT[k][r] = g_h[(size_t)(rb * 16 + r) * Hn + k0 + k];
        }
        __syncthreads();
#pragma unroll 10
        for (int k = 0; k < 50; k++) {
            float4 hv = *reinterpret_cast<const float4*>(&hT[k][rt * 4]);
            float4 wv = *reinterpret_cast<const float4*>(&Ws[k][ct * 4]);
            acc[0][0] += hv.x*wv.x; acc[0][1] += hv.x*wv.y; acc[0][2] += hv.x*wv.z; acc[0][3] += hv.x*wv.w;
            acc[1][0] += hv.y*wv.x; acc[1][1] += hv.y*wv.y; acc[1][2] += hv.y*wv.z; acc[1][3] += hv.y*wv.w;
            acc[2][0] += hv.z*wv.x; acc[2][1] += hv.z*wv.y; acc[2][2] += hv.z*wv.z; acc[2][3] += hv.z*wv.w;
            acc[3][0] += hv.w*wv.x; acc[3][1] += hv.w*wv.y; acc[3][2] += hv.w*wv.z; acc[3][3] += hv.w*wv.w;
        }
    }
#pragma unroll
    for (int i = 0; i < 4; i++) {
        int row = rb * 16 + rt * 4 + i;
        float4 v = make_float4(acc[i][0], acc[i][1], acc[i][2], acc[i][3]);
        *reinterpret_cast<float4*>(&g_part[(size_t)ks * (Bn * 128) + (size_t)row * 128 + ct * 4]) = v;
    }
}

// ---------------- head split-K stage B: combine + bias ----------------
__global__ void k_head_comb(const float* __restrict__ bmu, const float* __restrict__ blv)
{
    int b = blockIdx.x, tid = threadIdx.x;  // 128 threads
    if (tid < 100) {
        float s = 0.f;
#pragma unroll
        for (int ks = 0; ks < 4; ks++)
            s += g_part[(size_t)ks * (Bn * 128) + (size_t)b * 128 + tid];
        if (tid < 50) g_mu[b * Tn + tid] = s + bmu[tid];
        else          g_lv[b * Tn + (tid - 50)] = s + blv[tid - 50];
    }
}

// ---------------- logitsT[v][64] = rho[v,:] . alpha[t,:], fused softmax partials -----
// grid 391, 256 threads = 32 vt x 8 tq. Thread: v in {v0+vt+32i}, t in {tq*8..+7}.
__global__ void k_logitsT(const float* __restrict__ rho)
{
    __shared__ float rs[128][53];
    __shared__ float aT[50][64];
    int tid = threadIdx.x;
    int v0 = blockIdx.x * 128;
    int vt = tid & 31, tq = tid >> 5;
    float acc[4][8] = {};
    for (int k0 = 0; k0 < En; k0 += 50) {
        __syncthreads();
        for (int idx = tid; idx < 128 * 50; idx += 256) {
            int vi = idx / 50, k = idx % 50;
            int v = v0 + vi;
            rs[vi][k] = (v < Vn) ? rho[(size_t)v * En + k0 + k] : 0.f;
        }
        for (int idx = tid; idx < 50 * 64; idx += 256)
            aT[idx >> 6][idx & 63] = g_alphaT[(k0 << 6) + idx];
        __syncthreads();
#pragma unroll 5
        for (int k = 0; k < 50; k++) {
            float4 A0 = *reinterpret_cast<const float4*>(&aT[k][tq * 8]);
            float4 A1 = *reinterpret_cast<const float4*>(&aT[k][tq * 8 + 4]);
            float r0 = rs[vt][k], r1 = rs[vt + 32][k], r2 = rs[vt + 64][k], r3 = rs[vt + 96][k];
            acc[0][0] += r0*A0.x; acc[0][1] += r0*A0.y; acc[0][2] += r0*A0.z; acc[0][3] += r0*A0.w;
            acc[0][4] += r0*A1.x; acc[0][5] += r0*A1.y; acc[0][6] += r0*A1.z; acc[0][7] += r0*A1.w;
            acc[1][0] += r1*A0.x; acc[1][1] += r1*A0.y; acc[1][2] += r1*A0.z; acc[1][3] += r1*A0.w;
            acc[1][4] += r1*A1.x; acc[1][5] += r1*A1.y; acc[1][6] += r1*A1.z; acc[1][7] += r1*A1.w;
            acc[2][0] += r2*A0.x; acc[2][1] += r2*A0.y; acc[2][2] += r2*A0.z; acc[2][3] += r2*A0.w;
            acc[2][4] += r2*A1.x; acc[2][5] += r2*A1.y; acc[2][6] += r2*A1.z; acc[2][7] += r2*A1.w;
            acc[3][0] += r3*A0.x; acc[3][1] += r3*A0.y; acc[3][2] += r3*A0.z; acc[3][3] += r3*A0.w;
            acc[3][4] += r3*A1.x; acc[3][5] += r3*A1.y; acc[3][6] += r3*A1.z; acc[3][7] += r3*A1.w;
        }
    }
    // write logits tile (into g_betaT storage)
#pragma unroll
    for (int i = 0; i < 4; i++) {
        int v = v0 + vt + 32 * i;
        if (v < Vn) {
            *reinterpret_cast<float4*>(&g_betaT[(size_t)v * 64 + tq * 8]) =
                make_float4(acc[i][0], acc[i][1], acc[i][2], acc[i][3]);
            *reinterpret_cast<float4*>(&g_betaT[(size_t)v * 64 + tq * 8 + 4]) =
                make_float4(acc[i][4], acc[i][5], acc[i][6], acc[i][7]);
        }
    }
    // per-block online softmax partials per t (warp covers all 128 v)
    bool ok0 = (v0 + vt)      < Vn;
    bool ok1 = (v0 + vt + 32) < Vn;
    bool ok2 = (v0 + vt + 64) < Vn;
    bool ok3 = (v0 + vt + 96) < Vn;
#pragma unroll
    for (int j = 0; j < 8; j++) {
        float m = -1e30f;
        if (ok0) m = fmaxf(m, acc[0][j]);
        if (ok1) m = fmaxf(m, acc[1][j]);
        if (ok2) m = fmaxf(m, acc[2][j]);
        if (ok3) m = fmaxf(m, acc[3][j]);
#pragma unroll
        for (int o = 16; o; o >>= 1) m = fmaxf(m, __shfl_xor_sync(0xffffffffu, m, o));
        float e = 0.f;
        if (ok0) e += expf(acc[0][j] - m);
        if (ok1) e += expf(acc[1][j] - m);
        if (ok2) e += expf(acc[2][j] - m);
        if (ok3) e += expf(acc[3][j] - m);
#pragma unroll
        for (int o = 16; o; o >>= 1) e += __shfl_xor_sync(0xffffffffu, e, o);
        if (vt == 0) {
            g_bmax[blockIdx.x * 64 + tq * 8 + j] = m;
            g_bsum[blockIdx.x * 64 + tq * 8 + j] = e;
        }
    }
}

// ---------------- combine per-block softmax partials ----------------
__global__ void k_beta_comb()
{
    int t = threadIdx.x;  // 64
    float m = -1e30f;
#pragma unroll 8
    for (int b = 0; b < NLBLK; b++) m = fmaxf(m, g_bmax[b * 64 + t]);
    float s = 0.f;
#pragma unroll 8
    for (int b = 0; b < NLBLK; b++) s += g_bsum[b * 64 + t] * expf(g_bmax[b * 64 + t] - m);
    g_rmax[t] = m;
    g_rinv[t] = 1.0f / s;
}

// ---------------- scale logits -> beta in place ----------------
__global__ void k_beta_scale()
{
    __shared__ float sm[64], si[64];
    int tid = threadIdx.x;
    if (tid < 64) { sm[tid] = g_rmax[tid]; si[tid] = g_rinv[tid]; }
    __syncthreads();
    int idx = blockIdx.x * 256 + tid;  // 800000 float4 total
    float4* p = reinterpret_cast<float4*>(g_betaT);
    float4 x = p[idx];
    int t0 = (idx & 15) * 4;
    x.x = expf(x.x - sm[t0+0]) * si[t0+0];
    x.y = expf(x.y - sm[t0+1]) * si[t0+1];
    x.z = expf(x.z - sm[t0+2]) * si[t0+2];
    x.w = expf(x.w - sm[t0+3]) * si[t0+3];
    p[idx] = x;
}

// ---------------- kl + theta softmax; theta -> d_out ----------------
__global__ void k_theta_kl(float* __restrict__ out)
{
    int b = blockIdx.x, t = threadIdx.x;  // 64 threads
    __shared__ float red[64];
    bool ok = (t < Tn);
    float mu = 0.f, lv = 0.f;
    if (ok) { mu = g_mu[b * Tn + t]; lv = g_lv[b * Tn + t]; }
    float kle = ok ? (1.f + lv - mu * mu - expf(lv)) : 0.f;
    red[t] = kle; __syncthreads();
    for (int o = 32; o; o >>= 1) { if (t < o) red[t] += red[t + o]; __syncthreads(); }
    if (t == 0) g_kl[b] = -0.5f * red[0];
    __syncthreads();
    red[t] = ok ? mu : -1e30f; __syncthreads();
    for (int o = 32; o; o >>= 1) { if (t < o) red[t] = fmaxf(red[t], red[t + o]); __syncthreads(); }
    float mx = red[0]; __syncthreads();
    float e = ok ? expf(mu - mx) : 0.f;
    red[t] = e; __syncthreads();
    for (int o = 32; o; o >>= 1) { if (t < o) red[t] += red[t + o]; __syncthreads(); }
    float inv = 1.0f / red[0];
    if (ok) out[b * Tn + t] = e * inv;
}

// ---------------- recon[b]: thread-per-token dot over betaT[v][64] ----------------
__global__ void k_recon(const int* __restrict__ ids, const float* __restrict__ theta)
{
    __shared__ float th[64];
    __shared__ float red[256];
    int b = blockIdx.x, tid = threadIdx.x;
    if (tid < 64) th[tid] = (tid < Tn) ? theta[b * Tn + tid] : 0.f;
    __syncthreads();
    float acc = 0.f;
#pragma unroll 1
    for (int s = tid; s < Sn; s += 256) {
        int v = ids[b * Sn + s];
        if (v == 1 || v == 2) continue;
        const float4* p = reinterpret_cast<const float4*>(g_betaT + (size_t)v * 64);
        float d = 0.f;
#pragma unroll
        for (int i = 0; i < 16; i++) {
            float4 bv = p[i];
            float4 tv = *reinterpret_cast<const float4*>(&th[i * 4]);
            d += bv.x*tv.x + bv.y*tv.y + bv.z*tv.z + bv.w*tv.w;
        }
        acc += logf(d + 1e-5f);
    }
    red[tid] = acc; __syncthreads();
    for (int o = 128; o; o >>= 1) { if (tid < o) red[tid] += red[tid + o]; __syncthreads(); }
    if (tid == 0) g_recon[b] = -red[0];
}

// ---------------- final loss ----------------
__global__ void k_loss(float* __restrict__ out, int loss_idx)
{
    __shared__ float r1[1024];
    __shared__ float r2[1024];
    int t = threadIdx.x;
    r1[t] = g_recon[t]; r2[t] = g_kl[t];
    __syncthreads();
    for (int o = 512; o; o >>= 1) {
        if (t < o) { r1[t] += r1[t + o]; r2[t] += r2[t + o]; }
        __syncthreads();
    }
    if (t == 0) out[loss_idx] = (r1[0] + r2[0]) * (1.0f / (float)Bn);
}

// ---------------- launch ----------------
extern "C" void kernel_launch(void* const* d_in, const int* in_sizes, int n_in,
                              void* d_out, int out_size)
{
    const int*   ids   = (const int*)d_in[0];
    const float* rho   = (const float*)d_in[1];
    const float* alpha = (const float*)d_in[2];
    const float* W1    = (const float*)d_in[3];
    const float* b1    = (const float*)d_in[4];
    const float* Wmu   = (const float*)d_in[5];
    const float* bmu   = (const float*)d_in[6];
    const float* Wlv   = (const float*)d_in[7];
    const float* blv   = (const float*)d_in[8];
    float* out = (float*)d_out;

    void *p_x, *p_h;
    cudaGetSymbolAddress(&p_x, g_x);
    cudaGetSymbolAddress(&p_h, g_h);
    float* fx = (float*)p_x;
    float* fh = (float*)p_h;

    k_tobf16<<<2048, 256>>>(rho);
    k_alphaT<<<75, 256>>>(alpha);
    k_gather<<<Bn, 160>>>(ids);
    {
        dim3 g((Hn + 63) / 64, (Bn + 63) / 64);
        k_gemm<1><<<g, 256>>>(fx, W1, b1, fh, Bn, Hn, En);
    }
    k_head_part<<<dim3(4, 64), 128>>>(Wmu, Wlv);
    k_head_comb<<<Bn, 128>>>(bmu, blv);
    k_logitsT<<<NLBLK, 256>>>(rho);
    k_beta_comb<<<1, 64>>>();
    k_beta_scale<<<3125, 256>>>();
    k_theta_kl<<<Bn, 64>>>(out);
    k_recon<<<Bn, 256>>>(ids, out);
    k_loss<<<1, 1024>>>(out, out_size - 1);
}

// round 3
// speedup vs baseline: 1.2258x; 1.2258x over previous
#include <cuda_runtime.h>
#include <math.h>

#define Bn 1024
#define Sn 512
#define Vn 50000
#define En 300
#define Hn 800
#define Tn 50

// ---------------- scratch (device globals; no allocation) ----------------
__device__ float g_x[Bn * En];          // 1.2 MB
__device__ float g_h[Bn * Hn];          // 3.3 MB
__device__ float g_mu[Bn * Tn];
__device__ float g_lv[Bn * Tn];
__device__ float g_logits[Tn * Vn];     // 10 MB
__device__ float g_betaT[(size_t)Vn * 64]; // 12.8 MB, [v][t] padded to 64
__device__ float g_part[4 * Bn * 128];  // 2 MB head split-K partials
__device__ float g_rmax[Tn];
__device__ float g_rinv[Tn];
__device__ float g_recon[Bn];
__device__ float g_kl[Bn];

// ---------------- kernel 1: x[b,:] = (1/cnt) * sum_valid rho[id,:] ----------------
__global__ void k_gather(const int* __restrict__ ids, const float* __restrict__ rho)
{
    __shared__ int sid[Sn];
    __shared__ float s_inv;
    int b = blockIdx.x, tid = threadIdx.x;
    for (int i = tid; i < Sn; i += blockDim.x) {
        int v = ids[b * Sn + i];
        sid[i] = (v == 1 || v == 2) ? -1 : v;
    }
    __syncthreads();
    if (tid < 32) {
        int c = 0;
        for (int i = tid; i < Sn; i += 32) c += (sid[i] >= 0);
#pragma unroll
        for (int o = 16; o; o >>= 1) c += __shfl_down_sync(0xffffffffu, c, o);
        if (tid == 0) s_inv = 1.0f / (float)c;
    }
    __syncthreads();
    if (tid < En) {
        float a0 = 0.f, a1 = 0.f, a2 = 0.f, a3 = 0.f;
        float a4 = 0.f, a5 = 0.f, a6 = 0.f, a7 = 0.f;
        for (int s = 0; s < Sn; s += 8) {
            int v0 = sid[s + 0], v1 = sid[s + 1], v2 = sid[s + 2], v3 = sid[s + 3];
            int v4 = sid[s + 4], v5 = sid[s + 5], v6 = sid[s + 6], v7 = sid[s + 7];
            if (v0 >= 0) a0 += __ldg(&rho[v0 * En + tid]);
            if (v1 >= 0) a1 += __ldg(&rho[v1 * En + tid]);
            if (v2 >= 0) a2 += __ldg(&rho[v2 * En + tid]);
            if (v3 >= 0) a3 += __ldg(&rho[v3 * En + tid]);
            if (v4 >= 0) a4 += __ldg(&rho[v4 * En + tid]);
            if (v5 >= 0) a5 += __ldg(&rho[v5 * En + tid]);
            if (v6 >= 0) a6 += __ldg(&rho[v6 * En + tid]);
            if (v7 >= 0) a7 += __ldg(&rho[v7 * En + tid]);
        }
        float acc = ((a0 + a1) + (a2 + a3)) + ((a4 + a5) + (a6 + a7));
        g_x[b * En + tid] = acc * s_inv;
    }
}

// ---------------- generic tiled fp32 GEMM, C = A @ (B or B^T) + bias, opt relu -------
template <int TRANSB, int RELU>
__global__ void k_gemm(const float* __restrict__ A, const float* __restrict__ B,
                       const float* __restrict__ bias, float* __restrict__ C,
                       int M, int N, int K)
{
    __shared__ float As[20][65];
    __shared__ float Bs[20][68];
    int tid = threadIdx.x;
    int m0 = blockIdx.y * 64, n0 = blockIdx.x * 64;
    int my = (tid >> 4) * 4, nx = (tid & 15) * 4;
    float acc[4][4] = {};

    for (int k0 = 0; k0 < K; k0 += 20) {
#pragma unroll
        for (int p = 0; p < 5; p++) {
            int idx = tid + p * 256;
            {
                int i = idx / 20, j = idx % 20;
                int row = m0 + i;
                As[j][i] = (row < M) ? A[(size_t)row * K + k0 + j] : 0.f;
            }
            if (TRANSB) {
                int i = idx / 20, j = idx % 20;
                int col = n0 + i;
                Bs[j][i] = (col < N) ? B[(size_t)col * K + k0 + j] : 0.f;
            } else {
                int j = idx / 64, i = idx % 64;
                int col = n0 + i;
                Bs[j][i] = (col < N) ? B[(size_t)(k0 + j) * N + col] : 0.f;
            }
        }
        __syncthreads();
#pragma unroll
        for (int k = 0; k < 20; k++) {
            float a0 = As[k][my + 0], a1 = As[k][my + 1];
            float a2 = As[k][my + 2], a3 = As[k][my + 3];
            float4 bv = *reinterpret_cast<const float4*>(&Bs[k][nx]);
            acc[0][0] += a0 * bv.x; acc[0][1] += a0 * bv.y; acc[0][2] += a0 * bv.z; acc[0][3] += a0 * bv.w;
            acc[1][0] += a1 * bv.x; acc[1][1] += a1 * bv.y; acc[1][2] += a1 * bv.z; acc[1][3] += a1 * bv.w;
            acc[2][0] += a2 * bv.x; acc[2][1] += a2 * bv.y; acc[2][2] += a2 * bv.z; acc[2][3] += a2 * bv.w;
            acc[3][0] += a3 * bv.x; acc[3][1] += a3 * bv.y; acc[3][2] += a3 * bv.z; acc[3][3] += a3 * bv.w;
        }
        __syncthreads();
    }

#pragma unroll
    for (int i = 0; i < 4; i++) {
        int row = m0 + my + i;
        if (row >= M) continue;
#pragma unroll
        for (int j = 0; j < 4; j++) {
            int col = n0 + nx + j;
            if (col >= N) continue;
            float v = acc[i][j];
            if (bias) v += bias[col];
            if (RELU) v = fmaxf(v, 0.f);
            C[(size_t)row * N + col] = v;
        }
    }
}

// ---------------- head split-K stage A: partial[ks][row][c] over k-chunk of 200 ------
// grid (4 ksplit, 64 rowblk), 128 threads. c: 0..49 -> Wmu, 50..99 -> Wlv.
__global__ void k_head_part(const float* __restrict__ Wmu, const float* __restrict__ Wlv)
{
    __shared__ float Ws[50][132];
    __shared__ float hT[50][20];
    int tid = threadIdx.x;
    int ks = blockIdx.x, rb = blockIdx.y;
    int ct = tid & 31, rt = tid >> 5;
    float acc[4][4] = {};
    for (int sub = 0; sub < 4; sub++) {
        int k0 = ks * 200 + sub * 50;
        __syncthreads();
        for (int idx = tid; idx < 50 * 132; idx += 128) {
            int k = idx / 132, c = idx % 132;
            float v = 0.f;
            if (c < 50)       v = Wmu[(size_t)(k0 + k) * Tn + c];
            else if (c < 100) v = Wlv[(size_t)(k0 + k) * Tn + (c - 50)];
            Ws[k][c] = v;
        }
        for (int idx = tid; idx < 50 * 16; idx += 128) {
            int r = idx / 50, k = idx % 50;
            hT[k][r] = g_h[(size_t)(rb * 16 + r) * Hn + k0 + k];
        }
        __syncthreads();
#pragma unroll 10
        for (int k = 0; k < 50; k++) {
            float4 hv = *reinterpret_cast<const float4*>(&hT[k][rt * 4]);
            float4 wv = *reinterpret_cast<const float4*>(&Ws[k][ct * 4]);
            acc[0][0] += hv.x*wv.x; acc[0][1] += hv.x*wv.y; acc[0][2] += hv.x*wv.z; acc[0][3] += hv.x*wv.w;
            acc[1][0] += hv.y*wv.x; acc[1][1] += hv.y*wv.y; acc[1][2] += hv.y*wv.z; acc[1][3] += hv.y*wv.w;
            acc[2][0] += hv.z*wv.x; acc[2][1] += hv.z*wv.y; acc[2][2] += hv.z*wv.z; acc[2][3] += hv.z*wv.w;
            acc[3][0] += hv.w*wv.x; acc[3][1] += hv.w*wv.y; acc[3][2] += hv.w*wv.z; acc[3][3] += hv.w*wv.w;
        }
    }
#pragma unroll
    for (int i = 0; i < 4; i++) {
        int row = rb * 16 + rt * 4 + i;
        float4 v = make_float4(acc[i][0], acc[i][1], acc[i][2], acc[i][3]);
        *reinterpret_cast<float4*>(&g_part[(size_t)ks * (Bn * 128) + (size_t)row * 128 + ct * 4]) = v;
    }
}

// ---------------- head split-K stage B: combine + bias ----------------
__global__ void k_head_comb(const float* __restrict__ bmu, const float* __restrict__ blv)
{
    int b = blockIdx.x, tid = threadIdx.x;  // 128 threads
    if (tid < 100) {
        float s = 0.f;
#pragma unroll
        for (int ks = 0; ks < 4; ks++)
            s += g_part[(size_t)ks * (Bn * 128) + (size_t)b * 128 + tid];
        if (tid < 50) g_mu[b * Tn + tid] = s + bmu[tid];
        else          g_lv[b * Tn + (tid - 50)] = s + blv[tid - 50];
    }
}

// ---------------- beta softmax: pass 1 (row max + 1/sum) ----------------
__global__ void k_beta_stats()
{
    int t = blockIdx.x;      // 50 rows
    int tid = threadIdx.x;   // 256
    __shared__ float red[256];
    const float* row = g_logits + (size_t)t * Vn;
    float m = -1e30f;
    for (int v = tid; v < Vn; v += 256) m = fmaxf(m, row[v]);
    red[tid] = m; __syncthreads();
    for (int o = 128; o; o >>= 1) { if (tid < o) red[tid] = fmaxf(red[tid], red[tid + o]); __syncthreads(); }
    float M = red[0]; __syncthreads();
    float s = 0.f;
    for (int v = tid; v < Vn; v += 256) s += expf(row[v] - M);
    red[tid] = s; __syncthreads();
    for (int o = 128; o; o >>= 1) { if (tid < o) red[tid] += red[tid + o]; __syncthreads(); }
    if (tid == 0) { g_rmax[t] = M; g_rinv[t] = 1.0f / red[0]; }
}

// ---------------- beta softmax: pass 2, write transposed betaT[v*64+t] ----------------
__global__ void k_beta_write()
{
    __shared__ float tile[64][129];
    int v0 = blockIdx.x * 128;
    int tid = threadIdx.x;  // 256
    for (int idx = tid; idx < 64 * 128; idx += 256) {
        int t = idx >> 7, vi = idx & 127;
        float val = 0.f;
        int v = v0 + vi;
        if (t < Tn && v < Vn)
            val = expf(g_logits[(size_t)t * Vn + v] - g_rmax[t]) * g_rinv[t];
        tile[t][vi] = val;
    }
    __syncthreads();
    for (int idx = tid; idx < 64 * 128; idx += 256) {
        int vi = idx >> 6, t = idx & 63;
        int v = v0 + vi;
        if (v < Vn) g_betaT[(size_t)v * 64 + t] = tile[t][vi];
    }
}

// ---------------- kl + theta softmax; theta -> d_out ----------------
__global__ void k_theta_kl(float* __restrict__ out)
{
    int b = blockIdx.x, t = threadIdx.x;  // 64 threads
    __shared__ float red[64];
    bool ok = (t < Tn);
    float mu = 0.f, lv = 0.f;
    if (ok) { mu = g_mu[b * Tn + t]; lv = g_lv[b * Tn + t]; }
    float kle = ok ? (1.f + lv - mu * mu - expf(lv)) : 0.f;
    red[t] = kle; __syncthreads();
    for (int o = 32; o; o >>= 1) { if (t < o) red[t] += red[t + o]; __syncthreads(); }
    if (t == 0) g_kl[b] = -0.5f * red[0];
    __syncthreads();
    red[t] = ok ? mu : -1e30f; __syncthreads();
    for (int o = 32; o; o >>= 1) { if (t < o) red[t] = fmaxf(red[t], red[t + o]); __syncthreads(); }
    float mx = red[0]; __syncthreads();
    float e = ok ? expf(mu - mx) : 0.f;
    red[t] = e; __syncthreads();
    for (int o = 32; o; o >>= 1) { if (t < o) red[t] += red[t + o]; __syncthreads(); }
    float inv = 1.0f / red[0];
    if (ok) out[b * Tn + t] = e * inv;
}

// ---------------- recon[b]: thread-per-token dot over betaT[v][64] ----------------
__global__ void k_recon(const int* __restrict__ ids, const float* __restrict__ theta)
{
    __shared__ float th[64];
    __shared__ float red[256];
    int b = blockIdx.x, tid = threadIdx.x;
    if (tid < 64) th[tid] = (tid < Tn) ? theta[b * Tn + tid] : 0.f;
    __syncthreads();
    float acc = 0.f;
#pragma unroll 1
    for (int s = tid; s < Sn; s += 256) {
        int v = ids[b * Sn + s];
        if (v == 1 || v == 2) continue;
        const float4* p = reinterpret_cast<const float4*>(g_betaT + (size_t)v * 64);
        float d = 0.f;
#pragma unroll
        for (int i = 0; i < 16; i++) {
            float4 bv = p[i];
            float4 tv = *reinterpret_cast<const float4*>(&th[i * 4]);
            d += bv.x*tv.x + bv.y*tv.y + bv.z*tv.z + bv.w*tv.w;
        }
        acc += logf(d + 1e-5f);
    }
    red[tid] = acc; __syncthreads();
    for (int o = 128; o; o >>= 1) { if (tid < o) red[tid] += red[tid + o]; __syncthreads(); }
    if (tid == 0) g_recon[b] = -red[0];
}

// ---------------- final loss = mean(recon) + mean(kl) ----------------
__global__ void k_loss(float* __restrict__ out, int loss_idx)
{
    __shared__ float r1[1024];
    __shared__ float r2[1024];
    int t = threadIdx.x;  // 1024
    r1[t] = g_recon[t]; r2[t] = g_kl[t];
    __syncthreads();
    for (int o = 512; o; o >>= 1) {
        if (t < o) { r1[t] += r1[t + o]; r2[t] += r2[t + o]; }
        __syncthreads();
    }
    if (t == 0) out[loss_idx] = (r1[0] + r2[0]) * (1.0f / (float)Bn);
}

// ---------------- launch ----------------
extern "C" void kernel_launch(void* const* d_in, const int* in_sizes, int n_in,
                              void* d_out, int out_size)
{
    const int*   ids   = (const int*)d_in[0];
    const float* rho   = (const float*)d_in[1];
    const float* alpha = (const float*)d_in[2];
    const float* W1    = (const float*)d_in[3];
    const float* b1    = (const float*)d_in[4];
    const float* bmu   = (const float*)d_in[6];
    const float* Wmu   = (const float*)d_in[5];
    const float* Wlv   = (const float*)d_in[7];
    const float* blv   = (const float*)d_in[8];
    float* out = (float*)d_out;

    void *p_x, *p_h, *p_logits;
    cudaGetSymbolAddress(&p_x, g_x);
    cudaGetSymbolAddress(&p_h, g_h);
    cudaGetSymbolAddress(&p_logits, g_logits);
    float* fx = (float*)p_x;
    float* fh = (float*)p_h;
    float* flog = (float*)p_logits;

    // 1) x = gather(rho, ids) / count
    k_gather<<<Bn, 320>>>(ids, rho);

    // 2) h = relu(x @ W1 + b1)   [1024,300]x[300,800]
    {
        dim3 g((Hn + 63) / 64, (Bn + 63) / 64);
        k_gemm<0, 1><<<g, 256>>>(fx, W1, b1, fh, Bn, Hn, En);
    }
    // 3) mu/lv head via split-K (replaces two 55us degenerate GEMMs)
    k_head_part<<<dim3(4, 64), 128>>>(Wmu, Wlv);
    k_head_comb<<<Bn, 128>>>(bmu, blv);

    // 4) logits = alpha @ rho^T   [50,300]x[50000,300]^T
    {
        dim3 g((Vn + 63) / 64, (Tn + 63) / 64);
        k_gemm<1, 0><<<g, 256>>>(alpha, rho, (const float*)nullptr, flog, Tn, Vn, En);
    }
    // 5) beta = softmax(logits) over V, stored transposed/padded as betaT[v*64+t]
    k_beta_stats<<<Tn, 256>>>();
    k_beta_write<<<(Vn + 127) / 128, 256>>>();

    // 6) kl + theta softmax (theta written straight into d_out)
    k_theta_kl<<<Bn, 64>>>(out);

    // 7) recon loss per row (sparse token gather on betaT)
    k_recon<<<Bn, 256>>>(ids, out);

    // 8) loss scalar
    k_loss<<<1, 1024>>>(out, out_size - 1);
}

// round 4
// speedup vs baseline: 1.3898x; 1.1338x over previous
#include <cuda_runtime.h>
#include <math.h>

#define Bn 1024
#define Sn 512
#define Vn 50000
#define En 300
#define Hn 800
#define Tn 50
#define NSL 8              // beta-stats V slices
#define SLW 6250           // Vn / NSL

// ---------------- scratch (device globals; no allocation) ----------------
__device__ float g_x[Bn * En];
__device__ float g_h[Bn * Hn];
__device__ float g_mu[Bn * Tn];
__device__ float g_lv[Bn * Tn];
__device__ float g_logits[Tn * Vn];        // 10 MB
__device__ float g_betaT[(size_t)Vn * 64]; // 12.8 MB
__device__ float g_part[4 * Bn * 128];     // head split-K partials
__device__ float g_bmax[Tn * NSL];
__device__ float g_bsum[Tn * NSL];
__device__ float g_rmax[Tn];
__device__ float g_rinv[Tn];
__device__ float g_recon[Bn];
__device__ float g_kl[Bn];

// ---------------- kernel 1: x[b,:] = (1/cnt) * sum_valid rho[id,:] ----------------
__global__ void k_gather(const int* __restrict__ ids, const float* __restrict__ rho)
{
    __shared__ int sid[Sn];
    __shared__ float s_inv;
    int b = blockIdx.x, tid = threadIdx.x;
    for (int i = tid; i < Sn; i += blockDim.x) {
        int v = ids[b * Sn + i];
        sid[i] = (v == 1 || v == 2) ? -1 : v;
    }
    __syncthreads();
    if (tid < 32) {
        int c = 0;
        for (int i = tid; i < Sn; i += 32) c += (sid[i] >= 0);
#pragma unroll
        for (int o = 16; o; o >>= 1) c += __shfl_down_sync(0xffffffffu, c, o);
        if (tid == 0) s_inv = 1.0f / (float)c;
    }
    __syncthreads();
    if (tid < En) {
        float a0 = 0.f, a1 = 0.f, a2 = 0.f, a3 = 0.f;
        float a4 = 0.f, a5 = 0.f, a6 = 0.f, a7 = 0.f;
        for (int s = 0; s < Sn; s += 8) {
            int v0 = sid[s + 0], v1 = sid[s + 1], v2 = sid[s + 2], v3 = sid[s + 3];
            int v4 = sid[s + 4], v5 = sid[s + 5], v6 = sid[s + 6], v7 = sid[s + 7];
            if (v0 >= 0) a0 += __ldg(&rho[v0 * En + tid]);
            if (v1 >= 0) a1 += __ldg(&rho[v1 * En + tid]);
            if (v2 >= 0) a2 += __ldg(&rho[v2 * En + tid]);
            if (v3 >= 0) a3 += __ldg(&rho[v3 * En + tid]);
            if (v4 >= 0) a4 += __ldg(&rho[v4 * En + tid]);
            if (v5 >= 0) a5 += __ldg(&rho[v5 * En + tid]);
            if (v6 >= 0) a6 += __ldg(&rho[v6 * En + tid]);
            if (v7 >= 0) a7 += __ldg(&rho[v7 * En + tid]);
        }
        float acc = ((a0 + a1) + (a2 + a3)) + ((a4 + a5) + (a6 + a7));
        g_x[b * En + tid] = acc * s_inv;
    }
}

// ---------------- tiled fp32 GEMM (h = relu(x@W1+b1)) ----------------
template <int RELU>
__global__ void k_gemm(const float* __restrict__ A, const float* __restrict__ B,
                       const float* __restrict__ bias, float* __restrict__ C,
                       int M, int N, int K)
{
    __shared__ float As[20][65];
    __shared__ float Bs[20][68];
    int tid = threadIdx.x;
    int m0 = blockIdx.y * 64, n0 = blockIdx.x * 64;
    int my = (tid >> 4) * 4, nx = (tid & 15) * 4;
    float acc[4][4] = {};
    for (int k0 = 0; k0 < K; k0 += 20) {
#pragma unroll
        for (int p = 0; p < 5; p++) {
            int idx = tid + p * 256;
            {
                int i = idx / 20, j = idx % 20;
                int row = m0 + i;
                As[j][i] = (row < M) ? A[(size_t)row * K + k0 + j] : 0.f;
            }
            {
                int j = idx / 64, i = idx % 64;
                int col = n0 + i;
                Bs[j][i] = (col < N) ? B[(size_t)(k0 + j) * N + col] : 0.f;
            }
        }
        __syncthreads();
#pragma unroll
        for (int k = 0; k < 20; k++) {
            float a0 = As[k][my + 0], a1 = As[k][my + 1];
            float a2 = As[k][my + 2], a3 = As[k][my + 3];
            float4 bv = *reinterpret_cast<const float4*>(&Bs[k][nx]);
            acc[0][0] += a0 * bv.x; acc[0][1] += a0 * bv.y; acc[0][2] += a0 * bv.z; acc[0][3] += a0 * bv.w;
            acc[1][0] += a1 * bv.x; acc[1][1] += a1 * bv.y; acc[1][2] += a1 * bv.z; acc[1][3] += a1 * bv.w;
            acc[2][0] += a2 * bv.x; acc[2][1] += a2 * bv.y; acc[2][2] += a2 * bv.z; acc[2][3] += a2 * bv.w;
            acc[3][0] += a3 * bv.x; acc[3][1] += a3 * bv.y; acc[3][2] += a3 * bv.z; acc[3][3] += a3 * bv.w;
        }
        __syncthreads();
    }
#pragma unroll
    for (int i = 0; i < 4; i++) {
        int row = m0 + my + i;
        if (row >= M) continue;
#pragma unroll
        for (int j = 0; j < 4; j++) {
            int col = n0 + nx + j;
            if (col >= N) continue;
            float v = acc[i][j] + bias[col];
            if (RELU) v = fmaxf(v, 0.f);
            C[(size_t)row * N + col] = v;
        }
    }
}

// ---------------- head split-K ----------------
__global__ void k_head_part(const float* __restrict__ Wmu, const float* __restrict__ Wlv)
{
    __shared__ float Ws[50][132];
    __shared__ float hT[50][20];
    int tid = threadIdx.x;
    int ks = blockIdx.x, rb = blockIdx.y;
    int ct = tid & 31, rt = tid >> 5;
    float acc[4][4] = {};
    for (int sub = 0; sub < 4; sub++) {
        int k0 = ks * 200 + sub * 50;
        __syncthreads();
        for (int idx = tid; idx < 50 * 132; idx += 128) {
            int k = idx / 132, c = idx % 132;
            float v = 0.f;
            if (c < 50)       v = Wmu[(size_t)(k0 + k) * Tn + c];
            else if (c < 100) v = Wlv[(size_t)(k0 + k) * Tn + (c - 50)];
            Ws[k][c] = v;
        }
        for (int idx = tid; idx < 50 * 16; idx += 128) {
            int r = idx / 50, k = idx % 50;
            hT[k][r] = g_h[(size_t)(rb * 16 + r) * Hn + k0 + k];
        }
        __syncthreads();
#pragma unroll 10
        for (int k = 0; k < 50; k++) {
            float4 hv = *reinterpret_cast<const float4*>(&hT[k][rt * 4]);
            float4 wv = *reinterpret_cast<const float4*>(&Ws[k][ct * 4]);
            acc[0][0] += hv.x*wv.x; acc[0][1] += hv.x*wv.y; acc[0][2] += hv.x*wv.z; acc[0][3] += hv.x*wv.w;
            acc[1][0] += hv.y*wv.x; acc[1][1] += hv.y*wv.y; acc[1][2] += hv.y*wv.z; acc[1][3] += hv.y*wv.w;
            acc[2][0] += hv.z*wv.x; acc[2][1] += hv.z*wv.y; acc[2][2] += hv.z*wv.z; acc[2][3] += hv.z*wv.w;
            acc[3][0] += hv.w*wv.x; acc[3][1] += hv.w*wv.y; acc[3][2] += hv.w*wv.z; acc[3][3] += hv.w*wv.w;
        }
    }
#pragma unroll
    for (int i = 0; i < 4; i++) {
        int row = rb * 16 + rt * 4 + i;
        float4 v = make_float4(acc[i][0], acc[i][1], acc[i][2], acc[i][3]);
        *reinterpret_cast<float4*>(&g_part[(size_t)ks * (Bn * 128) + (size_t)row * 128 + ct * 4]) = v;
    }
}

__global__ void k_head_comb(const float* __restrict__ bmu, const float* __restrict__ blv)
{
    int b = blockIdx.x, tid = threadIdx.x;
    if (tid < 100) {
        float s = 0.f;
#pragma unroll
        for (int ks = 0; ks < 4; ks++)
            s += g_part[(size_t)ks * (Bn * 128) + (size_t)b * 128 + tid];
        if (tid < 50) g_mu[b * Tn + tid] = s + bmu[tid];
        else          g_lv[b * Tn + (tid - 50)] = s + blv[tid - 50];
    }
}

// ---------------- logits = alpha @ rho^T via tf32 mma.sync ----------------
// Block: 256 threads (8 warps: 4 in M x 2 in N). Out tile 64(t) x 64(v).
// K = 304 (300 + 4 zero pad), 2 chunks of 152 (19 k-steps of 8).
// smem row stride 156 floats -> conflict-free fragment loads.
#define KCH 152
#define LDK 156
__global__ void k_logits_mma(const float* __restrict__ alpha, const float* __restrict__ rho)
{
    extern __shared__ float sm[];
    float* As = sm;                 // [64][156]
    float* Bs = sm + 64 * LDK;      // [64][156]
    int tid = threadIdx.x;
    int lane = tid & 31, warp = tid >> 5;
    int gid = lane >> 2, tig = lane & 3;
    int wm = warp >> 1, wn = warp & 1;
    int v0 = blockIdx.x * 64;
    float c[4][4] = {};

    for (int ch = 0; ch < 2; ch++) {
        int kbase = ch * KCH;
        __syncthreads();
        // load A tile: rows t (zero for t>=50), cols kbase..kbase+151 (zero pad beyond 299)
        for (int i = tid; i < 64 * 39; i += 256) {
            int row = i / 39, q = i % 39;
            int col = q * 4;
            int gk = kbase + col;
            float4 v = make_float4(0.f, 0.f, 0.f, 0.f);
            if (q < 38 && row < Tn && gk < En)
                v = *reinterpret_cast<const float4*>(&alpha[(size_t)row * En + gk]);
            unsigned t0, t1, t2, t3;
            asm("cvt.rna.tf32.f32 %0, %1;" : "=r"(t0) : "f"(v.x));
            asm("cvt.rna.tf32.f32 %0, %1;" : "=r"(t1) : "f"(v.y));
            asm("cvt.rna.tf32.f32 %0, %1;" : "=r"(t2) : "f"(v.z));
            asm("cvt.rna.tf32.f32 %0, %1;" : "=r"(t3) : "f"(v.w));
            float4 o = make_float4(__uint_as_float(t0), __uint_as_float(t1),
                                   __uint_as_float(t2), __uint_as_float(t3));
            *reinterpret_cast<float4*>(&As[row * LDK + col]) = o;
        }
        // load B tile: rows v (zero for v>=Vn)
        for (int i = tid; i < 64 * 39; i += 256) {
            int row = i / 39, q = i % 39;
            int col = q * 4;
            int gk = kbase + col;
            int v = v0 + row;
            float4 x = make_float4(0.f, 0.f, 0.f, 0.f);
            if (q < 38 && v < Vn && gk < En)
                x = *reinterpret_cast<const float4*>(&rho[(size_t)v * En + gk]);
            unsigned t0, t1, t2, t3;
            asm("cvt.rna.tf32.f32 %0, %1;" : "=r"(t0) : "f"(x.x));
            asm("cvt.rna.tf32.f32 %0, %1;" : "=r"(t1) : "f"(x.y));
            asm("cvt.rna.tf32.f32 %0, %1;" : "=r"(t2) : "f"(x.z));
            asm("cvt.rna.tf32.f32 %0, %1;" : "=r"(t3) : "f"(x.w));
            float4 o = make_float4(__uint_as_float(t0), __uint_as_float(t1),
                                   __uint_as_float(t2), __uint_as_float(t3));
            *reinterpret_cast<float4*>(&Bs[row * LDK + col]) = o;
        }
        __syncthreads();

        const float* Ap = As + (wm * 16 + gid) * LDK + tig;
#pragma unroll
        for (int ks = 0; ks < 19; ks++) {
            int k = ks * 8;
            unsigned a0 = __float_as_uint(Ap[k]);
            unsigned a1 = __float_as_uint(Ap[8 * LDK + k]);
            unsigned a2 = __float_as_uint(Ap[k + 4]);
            unsigned a3 = __float_as_uint(Ap[8 * LDK + k + 4]);
#pragma unroll
            for (int nt = 0; nt < 4; nt++) {
                const float* Bp = Bs + (wn * 32 + nt * 8 + gid) * LDK + tig + k;
                unsigned b0 = __float_as_uint(Bp[0]);
                unsigned b1 = __float_as_uint(Bp[4]);
                asm volatile(
                    "mma.sync.aligned.m16n8k8.row.col.f32.tf32.tf32.f32 "
                    "{%0,%1,%2,%3}, {%4,%5,%6,%7}, {%8,%9}, {%0,%1,%2,%3};"
                    : "+f"(c[nt][0]), "+f"(c[nt][1]), "+f"(c[nt][2]), "+f"(c[nt][3])
                    : "r"(a0), "r"(a1), "r"(a2), "r"(a3), "r"(b0), "r"(b1));
            }
        }
    }

    int r0 = wm * 16 + gid;
    int colbase = v0 + wn * 32 + tig * 2;
#pragma unroll
    for (int nt = 0; nt < 4; nt++) {
        int col = colbase + nt * 8;
        if (col < Vn) {
            if (r0 < Tn)
                *reinterpret_cast<float2*>(&g_logits[(size_t)r0 * Vn + col]) =
                    make_float2(c[nt][0], c[nt][1]);
            if (r0 + 8 < Tn)
                *reinterpret_cast<float2*>(&g_logits[(size_t)(r0 + 8) * Vn + col]) =
                    make_float2(c[nt][2], c[nt][3]);
        }
    }
}

// ---------------- beta softmax: sliced pass 1 partials ----------------
__global__ void k_beta_part()
{
    int t = blockIdx.x, sl = blockIdx.y, tid = threadIdx.x;  // 256 threads
    __shared__ float red[256];
    const float* row = g_logits + (size_t)t * Vn + sl * SLW;
    float m = -1e30f;
    for (int v = tid; v < SLW; v += 256) m = fmaxf(m, row[v]);
    red[tid] = m; __syncthreads();
    for (int o = 128; o; o >>= 1) { if (tid < o) red[tid] = fmaxf(red[tid], red[tid + o]); __syncthreads(); }
    float M = red[0]; __syncthreads();
    float s = 0.f;
    for (int v = tid; v < SLW; v += 256) s += expf(row[v] - M);
    red[tid] = s; __syncthreads();
    for (int o = 128; o; o >>= 1) { if (tid < o) red[tid] += red[tid + o]; __syncthreads(); }
    if (tid == 0) { g_bmax[t * NSL + sl] = M; g_bsum[t * NSL + sl] = red[0]; }
}

// ---------------- combine slice partials ----------------
__global__ void k_beta_comb()
{
    int t = threadIdx.x;  // 64
    if (t < Tn) {
        float m = -1e30f;
#pragma unroll
        for (int s = 0; s < NSL; s++) m = fmaxf(m, g_bmax[t * NSL + s]);
        float sum = 0.f;
#pragma unroll
        for (int s = 0; s < NSL; s++) sum += g_bsum[t * NSL + s] * expf(g_bmax[t * NSL + s] - m);
        g_rmax[t] = m;
        g_rinv[t] = 1.0f / sum;
    }
}

// ---------------- beta pass 2: write transposed betaT[v*64+t] ----------------
__global__ void k_beta_write()
{
    __shared__ float tile[64][129];
    int v0 = blockIdx.x * 128;
    int tid = threadIdx.x;  // 256
    for (int idx = tid; idx < 64 * 128; idx += 256) {
        int t = idx >> 7, vi = idx & 127;
        float val = 0.f;
        int v = v0 + vi;
        if (t < Tn && v < Vn)
            val = expf(g_logits[(size_t)t * Vn + v] - g_rmax[t]) * g_rinv[t];
        tile[t][vi] = val;
    }
    __syncthreads();
    for (int idx = tid; idx < 64 * 128; idx += 256) {
        int vi = idx >> 6, t = idx & 63;
        int v = v0 + vi;
        if (v < Vn) g_betaT[(size_t)v * 64 + t] = tile[t][vi];
    }
}

// ---------------- kl + theta softmax ----------------
__global__ void k_theta_kl(float* __restrict__ out)
{
    int b = blockIdx.x, t = threadIdx.x;  // 64 threads
    __shared__ float red[64];
    bool ok = (t < Tn);
    float mu = 0.f, lv = 0.f;
    if (ok) { mu = g_mu[b * Tn + t]; lv = g_lv[b * Tn + t]; }
    float kle = ok ? (1.f + lv - mu * mu - expf(lv)) : 0.f;
    red[t] = kle; __syncthreads();
    for (int o = 32; o; o >>= 1) { if (t < o) red[t] += red[t + o]; __syncthreads(); }
    if (t == 0) g_kl[b] = -0.5f * red[0];
    __syncthreads();
    red[t] = ok ? mu : -1e30f; __syncthreads();
    for (int o = 32; o; o >>= 1) { if (t < o) red[t] = fmaxf(red[t], red[t + o]); __syncthreads(); }
    float mx = red[0]; __syncthreads();
    float e = ok ? expf(mu - mx) : 0.f;
    red[t] = e; __syncthreads();
    for (int o = 32; o; o >>= 1) { if (t < o) red[t] += red[t + o]; __syncthreads(); }
    float inv = 1.0f / red[0];
    if (ok) out[b * Tn + t] = e * inv;
}

// ---------------- recon ----------------
__global__ void k_recon(const int* __restrict__ ids, const float* __restrict__ theta)
{
    __shared__ float th[64];
    __shared__ float red[256];
    int b = blockIdx.x, tid = threadIdx.x;
    if (tid < 64) th[tid] = (tid < Tn) ? theta[b * Tn + tid] : 0.f;
    __syncthreads();
    float acc = 0.f;
#pragma unroll 1
    for (int s = tid; s < Sn; s += 256) {
        int v = ids[b * Sn + s];
        if (v == 1 || v == 2) continue;
        const float4* p = reinterpret_cast<const float4*>(g_betaT + (size_t)v * 64);
        float d = 0.f;
#pragma unroll
        for (int i = 0; i < 16; i++) {
            float4 bv = p[i];
            float4 tv = *reinterpret_cast<const float4*>(&th[i * 4]);
            d += bv.x*tv.x + bv.y*tv.y + bv.z*tv.z + bv.w*tv.w;
        }
        acc += logf(d + 1e-5f);
    }
    red[tid] = acc; __syncthreads();
    for (int o = 128; o; o >>= 1) { if (tid < o) red[tid] += red[tid + o]; __syncthreads(); }
    if (tid == 0) g_recon[b] = -red[0];
}

// ---------------- final loss ----------------
__global__ void k_loss(float* __restrict__ out, int loss_idx)
{
    __shared__ float r1[1024];
    __shared__ float r2[1024];
    int t = threadIdx.x;
    r1[t] = g_recon[t]; r2[t] = g_kl[t];
    __syncthreads();
    for (int o = 512; o; o >>= 1) {
        if (t < o) { r1[t] += r1[t + o]; r2[t] += r2[t + o]; }
        __syncthreads();
    }
    if (t == 0) out[loss_idx] = (r1[0] + r2[0]) * (1.0f / (float)Bn);
}

// ---------------- launch ----------------
extern "C" void kernel_launch(void* const* d_in, const int* in_sizes, int n_in,
                              void* d_out, int out_size)
{
    const int*   ids   = (const int*)d_in[0];
    const float* rho   = (const float*)d_in[1];
    const float* alpha = (const float*)d_in[2];
    const float* W1    = (const float*)d_in[3];
    const float* b1    = (const float*)d_in[4];
    const float* Wmu   = (const float*)d_in[5];
    const float* bmu   = (const float*)d_in[6];
    const float* Wlv   = (const float*)d_in[7];
    const float* blv   = (const float*)d_in[8];
    float* out = (float*)d_out;

    void *p_x, *p_h;
    cudaGetSymbolAddress(&p_x, g_x);
    cudaGetSymbolAddress(&p_h, g_h);
    float* fx = (float*)p_x;
    float* fh = (float*)p_h;

    // 1) x = gather(rho, ids) / count
    k_gather<<<Bn, 320>>>(ids, rho);

    // 2) h = relu(x @ W1 + b1)
    {
        dim3 g((Hn + 63) / 64, (Bn + 63) / 64);
        k_gemm<1><<<g, 256>>>(fx, W1, b1, fh, Bn, Hn, En);
    }
    // 3) mu/lv head via split-K
    k_head_part<<<dim3(4, 64), 128>>>(Wmu, Wlv);
    k_head_comb<<<Bn, 128>>>(bmu, blv);

    // 4) logits = alpha @ rho^T via tf32 tensor cores
    {
        int smem = 2 * 64 * LDK * sizeof(float);  // 79872 B
        cudaFuncSetAttribute(k_logits_mma, cudaFuncAttributeMaxDynamicSharedMemorySize, smem);
        k_logits_mma<<<(Vn + 63) / 64, 256, smem>>>(alpha, rho);
    }
    // 5) beta softmax (sliced stats + combine + transposed write)
    k_beta_part<<<dim3(Tn, NSL), 256>>>();
    k_beta_comb<<<1, 64>>>();
    k_beta_write<<<(Vn + 127) / 128, 256>>>();

    // 6) kl + theta softmax
    k_theta_kl<<<Bn, 64>>>(out);

    // 7) recon
    k_recon<<<Bn, 256>>>(ids, out);

    // 8) loss
    k_loss<<<1, 1024>>>(out, out_size - 1);
}